// round 5
// baseline (speedup 1.0000x reference)
#include <cuda_runtime.h>
#include <cuda_fp16.h>
#include <cstdint>

// ---------------- problem constants ----------------
#define NB_ROWS   16384
#define N_IN      256
#define N_OUT     256
#define N_BASES   31
#define N_J       33          // 32 buckets + the all-zero bucket (xn == 1.0)
#define TB        112         // rows per block
#define RPW       14          // rows per warp (8 warps x 14 = 112)
#define NBLK      147         // ceil(16384/112)
#define BPAD      16576       // padded row count for RXJ (mult of 32, >= 147*112)

// ---------------- device scratch (no allocation allowed) ----------------
__device__ __align__(16) __half g_W2h[N_IN * N_J * N_OUT];  // [i][j][o] fp16, 4.33 MB
__device__ float        g_BWT[N_IN * N_OUT];          // [i][o]  256 KB
__device__ unsigned int g_RXJ[N_IN * BPAD];           // [i][row]: relu(x) fp32, j in low 6 mantissa bits
__device__ unsigned int g_minU[N_IN];
__device__ unsigned int g_maxU[N_IN];
__device__ float        g_minv[N_IN];
__device__ float        g_rcp[N_IN];                  // RN(1/(max-min+1e-8)) per column

// ---------------- helpers ----------------
__device__ __forceinline__ unsigned int enc_f(float f) {
    unsigned int u = __float_as_uint(f);
    return (u & 0x80000000u) ? ~u : (u | 0x80000000u);
}
__device__ __forceinline__ float dec_f(unsigned int e) {
    unsigned int u = (e & 0x80000000u) ? (e ^ 0x80000000u) : ~e;
    return __uint_as_float(u);
}
__device__ __forceinline__ unsigned long long pk2(float a, float b) {
    unsigned long long r;
    asm("mov.b64 %0, {%1, %2};" : "=l"(r) : "f"(a), "f"(b));
    return r;
}
__device__ __forceinline__ void fma2(unsigned long long& d, unsigned long long a, unsigned long long b) {
    asm("fma.rn.f32x2 %0, %1, %2, %0;" : "+l"(d) : "l"(a), "l"(b));
}
__device__ __forceinline__ void add2(unsigned long long& d, unsigned long long a) {
    asm("add.rn.f32x2 %0, %1, %0;" : "+l"(d) : "l"(a));
}
__device__ __forceinline__ float lo32(unsigned long long v) {
    return __uint_as_float((unsigned int)(v & 0xFFFFFFFFull));
}
__device__ __forceinline__ float hi32(unsigned long long v) {
    return __uint_as_float((unsigned int)(v >> 32));
}
// fp16x2 (as u32) -> packed f32x2 (as u64)
__device__ __forceinline__ unsigned long long h2_to_f2(unsigned int h) {
    float2 f = __half22float2(*reinterpret_cast<__half2*>(&h));
    return pk2(f.x, f.y);
}

// ---------------- K0: init min/max atomics ----------------
__global__ void k_init() {
    int t = threadIdx.x;
    g_minU[t] = 0xFFFFFFFFu;
    g_maxU[t] = 0x00000000u;
}

// ---------------- K1: per-column min/max ----------------
__global__ void k_minmax(const float* __restrict__ x) {
    int c  = threadIdx.x;
    int r0 = blockIdx.x * 128;
    float mn = __int_as_float(0x7f800000);
    float mx = __int_as_float(0xff800000);
    for (int r = r0; r < r0 + 128; r++) {
        float v = x[r * N_IN + c];
        mn = fminf(mn, v);
        mx = fmaxf(mx, v);
    }
    atomicMin(&g_minU[c], enc_f(mn));
    atomicMax(&g_maxU[c], enc_f(mx));
}

// ---------------- K2: per-column reciprocal (XLA's div->mul(rcp) rewrite) ----------------
__global__ void k_denom() {
    int i = threadIdx.x;
    float mn = dec_f(g_minU[i]);
    float mx = dec_f(g_maxU[i]);
    float d  = __fadd_rn(__fsub_rn(mx, mn), 1e-8f);
    g_minv[i] = mn;
    g_rcp[i]  = __frcp_rn(d);                          // == div.rn.f32(1.0, d)
}

// ---------------- K3: bucketize + transpose -> RXJ[i][row] ----------------
__global__ void k_rxj(const float* __restrict__ x) {
    __shared__ unsigned int s[32][33];
    int tx = threadIdx.x, ty = threadIdx.y;
    int c0 = blockIdx.x * 32;
    int r0 = blockIdx.y * 32;
    int c  = c0 + tx;
    float mn = g_minv[c];
    float rc = g_rcp[c];
#pragma unroll
    for (int k = 0; k < 4; k++) {
        int r = r0 + ty + 8 * k;
        unsigned int w = 0u;
        if (r < NB_ROWS) {
            float v  = x[r * N_IN + c];
            float xn = __fmul_rn(__fsub_rn(v, mn), rc);   // bit-matches reference
            int j = (int)(xn * 32.0f);
            j = min(max(j, 0), 32);
            float rx = fmaxf(v, 0.0f);
            w = (__float_as_uint(rx) & 0xFFFFFFC0u) | (unsigned int)j;
        }
        s[ty + 8 * k][tx] = w;
    }
    __syncthreads();
#pragma unroll
    for (int k = 0; k < 4; k++) {
        int c2 = c0 + ty + 8 * k;
        int r2 = r0 + tx;
        g_RXJ[c2 * BPAD + r2] = s[tx][ty + 8 * k];
    }
}

// ---------------- K4: transpose base_weight [O][I] -> BWT [I][O] ----------------
__global__ void k_tbw(const float* __restrict__ bw) {
    __shared__ float s[32][33];
    int tx = threadIdx.x, ty = threadIdx.y;
    int a0 = blockIdx.y * 32;
    int b0 = blockIdx.x * 32;
#pragma unroll
    for (int k = 0; k < 4; k++)
        s[ty + 8 * k][tx] = bw[(a0 + ty + 8 * k) * N_IN + b0 + tx];
    __syncthreads();
#pragma unroll
    for (int k = 0; k < 4; k++)
        g_BWT[(b0 + ty + 8 * k) * N_OUT + a0 + tx] = s[tx][ty + 8 * k];
}

// ---------------- K5: build W2[i][j][o] in fp16 ----------------
__global__ void k_w2(const float* __restrict__ sw, const float* __restrict__ sc) {
    int i = blockIdx.x;
    int o = threadIdx.x;
    float s = sc[o * N_IN + i];
    float w[N_BASES];
#pragma unroll
    for (int k = 0; k < N_BASES; k++)
        w[k] = sw[o * (N_IN * N_BASES) + i * N_BASES + k] * s;
    __half* dst = g_W2h + (i * N_J) * N_OUT + o;
#pragma unroll
    for (int j = 0; j < 32; j++) {
        float a = 0.0f;
#pragma unroll
        for (int l = 0; l < 5; l++) {
            int shift = j >> (5 - l);
            int half  = (j >> (4 - l)) & 1;
            int k     = (1 << l) - 1 + shift;
            a += half ? -w[k] : w[k];
        }
        dst[j * N_OUT] = __float2half_rn(a);
    }
    dst[32 * N_OUT] = __float2half_rn(0.0f);   // all-zero bucket (xn == 1.0)
}

// ---------------- K6: main fused kernel ----------------
// 147 blocks x 256 threads. warp g = tid>>5 handles rows rbase..rbase+13;
// thread o8 = tid&31 handles outputs o8*8..o8*8+7 (one LDG.128 of 8 fp16 per gather).
__global__ __launch_bounds__(256, 1) void k_main(float* __restrict__ out) {
    int tid   = threadIdx.x;
    int o8    = tid & 31;
    int g     = tid >> 5;
    int rbase = blockIdx.x * TB + g * RPW;

    unsigned long long acc[RPW][4];
#pragma unroll
    for (int r = 0; r < RPW; r++)
#pragma unroll
        for (int p = 0; p < 4; p++) acc[r][p] = 0ull;

    const uint4*  __restrict__ W2v = reinterpret_cast<const uint4*>(g_W2h);  // row = 32 uint4
    const float4* __restrict__ BWv = reinterpret_cast<const float4*>(g_BWT);
    const uint2*  __restrict__ RXv = reinterpret_cast<const uint2*>(g_RXJ);

    for (int i = 0; i < N_IN; i++) {
        float4 b0 = BWv[i * (N_OUT / 4) + o8 * 2];
        float4 b1 = BWv[i * (N_OUT / 4) + o8 * 2 + 1];
        unsigned long long bwp[4];
        bwp[0] = pk2(b0.x, b0.y); bwp[1] = pk2(b0.z, b0.w);
        bwp[2] = pk2(b1.x, b1.y); bwp[3] = pk2(b1.z, b1.w);

        const uint4* slice = W2v + (size_t)i * (N_J * (N_OUT / 8)) + o8;
        const uint2* rxr   = RXv + i * (BPAD / 2) + (rbase >> 1);

        unsigned int ws[RPW];
#pragma unroll
        for (int c = 0; c < RPW / 2; c++) {           // 7 uniform LDG.64 broadcasts
            uint2 q = rxr[c];
            ws[2 * c]     = q.x;
            ws[2 * c + 1] = q.y;
        }
#pragma unroll
        for (int r = 0; r < RPW; r++) {
            unsigned int w = ws[r];
            uint4 gv = slice[(w & 63u) * (N_OUT / 8)];         // L1-resident LDG.128, 8 fp16
            float rx = __uint_as_float(w);                     // low 6 bits: 2^-17 rel noise
            unsigned long long rxx = pk2(rx, rx);
            fma2(acc[r][0], bwp[0], rxx);  add2(acc[r][0], h2_to_f2(gv.x));
            fma2(acc[r][1], bwp[1], rxx);  add2(acc[r][1], h2_to_f2(gv.y));
            fma2(acc[r][2], bwp[2], rxx);  add2(acc[r][2], h2_to_f2(gv.z));
            fma2(acc[r][3], bwp[3], rxx);  add2(acc[r][3], h2_to_f2(gv.w));
        }
        if (i & 1) __syncthreads();       // keep all 8 warps within a 2-slice (~34KB) L1 window
    }

#pragma unroll
    for (int r = 0; r < RPW; r++) {
        int row = rbase + r;
        if (row < NB_ROWS) {
            float4 o0, o1;
            o0.x = lo32(acc[r][0]); o0.y = hi32(acc[r][0]);
            o0.z = lo32(acc[r][1]); o0.w = hi32(acc[r][1]);
            o1.x = lo32(acc[r][2]); o1.y = hi32(acc[r][2]);
            o1.z = lo32(acc[r][3]); o1.w = hi32(acc[r][3]);
            float4* dst = reinterpret_cast<float4*>(out) + row * (N_OUT / 4) + o8 * 2;
            dst[0] = o0;
            dst[1] = o1;
        }
    }
}

// ---------------- launch ----------------
extern "C" void kernel_launch(void* const* d_in, const int* in_sizes, int n_in,
                              void* d_out, int out_size) {
    const float* x  = (const float*)d_in[0];   // [16384, 256]
    const float* bw = (const float*)d_in[1];   // [256, 256]
    const float* sw = (const float*)d_in[2];   // [256, 256, 31]
    const float* sc = (const float*)d_in[3];   // [256, 256]
    float* out = (float*)d_out;

    k_init  <<<1, 256>>>();
    k_minmax<<<128, 256>>>(x);
    k_denom <<<1, 256>>>();
    k_rxj   <<<dim3(8, BPAD / 32), dim3(32, 8)>>>(x);
    k_tbw   <<<dim3(8, 8), dim3(32, 8)>>>(bw);
    k_w2    <<<256, 256>>>(sw, sc);
    k_main  <<<NBLK, 256>>>(out);
}

// round 7
// speedup vs baseline: 1.4752x; 1.4752x over previous
#include <cuda_runtime.h>
#include <cuda_fp16.h>
#include <cstdint>

// ================= problem constants =================
#define NB_ROWS  16384
#define N_IN     256
#define N_OUT    256
#define N_BASES  31
#define MTILE    112                 // rows per CTA
#define RPW      14                  // rows per warp (8 warps)
#define NCTA     147                 // ceil(16384/112)
#define BPAD     16576               // padded rows (>= 146*112+112, mult of 32)

// smem: 2 stages x 4 i-slices x 16KB + zero row
#define SM_STAGE(s) ((s) * 65536)
#define SM_ZERO     131072
#define SMEM_TOTAL  (131072 + 512)

// ================= device scratch =================
__device__ __align__(16) __half   g_W2T[N_IN * 32 * N_OUT];  // [i][j<32][o] fp16, 4 MB
__device__ __align__(16) __half   g_BW16[N_IN * N_OUT];      // [i][o] fp16
__device__ uint32_t               g_RJ[N_IN * BPAD];         // [i][row]: (j<<16)|rx_fp16
__device__ unsigned int g_minU[N_IN];
__device__ unsigned int g_maxU[N_IN];
__device__ float        g_minv[N_IN];
__device__ float        g_rcp[N_IN];

// ================= helpers =================
__device__ __forceinline__ unsigned int enc_f(float f) {
    unsigned int u = __float_as_uint(f);
    return (u & 0x80000000u) ? ~u : (u | 0x80000000u);
}
__device__ __forceinline__ float dec_f(unsigned int e) {
    unsigned int u = (e & 0x80000000u) ? (e ^ 0x80000000u) : ~e;
    return __uint_as_float(u);
}
__device__ __forceinline__ uint32_t smem_u32(const void* p) {
    uint32_t a;
    asm("{ .reg .u64 t; cvta.to.shared.u64 t, %1; cvt.u32.u64 %0, t; }" : "=r"(a) : "l"(p));
    return a;
}
__device__ __forceinline__ unsigned long long pk2(float a, float b) {
    unsigned long long r;
    asm("mov.b64 %0, {%1, %2};" : "=l"(r) : "f"(a), "f"(b));
    return r;
}
__device__ __forceinline__ void addf2(unsigned long long& d, unsigned long long a) {
    asm("add.rn.f32x2 %0, %1, %0;" : "+l"(d) : "l"(a));
}
__device__ __forceinline__ float lo32(unsigned long long v) {
    return __uint_as_float((unsigned int)(v & 0xFFFFFFFFull));
}
__device__ __forceinline__ float hi32(unsigned long long v) {
    return __uint_as_float((unsigned int)(v >> 32));
}
__device__ __forceinline__ void hadd2a(uint32_t& acc, uint32_t v) {
    asm("add.rn.f16x2 %0, %1, %0;" : "+r"(acc) : "r"(v));
}
__device__ __forceinline__ void hfma2a(uint32_t& acc, uint32_t a, uint32_t b) {
    asm("fma.rn.f16x2 %0, %1, %2, %0;" : "+r"(acc) : "r"(a), "r"(b));
}
__device__ __forceinline__ unsigned long long h2f2(uint32_t h) {
    __half2 hh = *reinterpret_cast<__half2*>(&h);
    float2 f = __half22float2(hh);
    return pk2(f.x, f.y);
}
__device__ __forceinline__ void cpa16(uint32_t saddr, const void* g) {
    asm volatile("cp.async.cg.shared.global [%0], [%1], 16;" :: "r"(saddr), "l"(g));
}

// ================= prep kernels =================
__global__ void k_init() {
    int t = threadIdx.x;
    g_minU[t] = 0xFFFFFFFFu;
    g_maxU[t] = 0x00000000u;
}

__global__ void k_minmax(const float* __restrict__ x) {
    int c  = threadIdx.x;
    int r0 = blockIdx.x * 128;
    float mn = __int_as_float(0x7f800000);
    float mx = __int_as_float(0xff800000);
    for (int r = r0; r < r0 + 128; r++) {
        float v = x[r * N_IN + c];
        mn = fminf(mn, v);
        mx = fmaxf(mx, v);
    }
    atomicMin(&g_minU[c], enc_f(mn));
    atomicMax(&g_maxU[c], enc_f(mx));
}

__global__ void k_denom() {   // XLA rewrites div(A,bcast(B)) -> mul(A,bcast(1/B))
    int i = threadIdx.x;
    float mn = dec_f(g_minU[i]);
    float mx = dec_f(g_maxU[i]);
    float d  = __fadd_rn(__fsub_rn(mx, mn), 1e-8f);
    g_minv[i] = mn;
    g_rcp[i]  = __frcp_rn(d);
}

// bucketize + relu fp16, transposed -> g_RJ[i][row] = (j<<16)|rx_h
__global__ void k_rxj(const float* __restrict__ x) {
    __shared__ uint32_t s[32][33];
    int tx = threadIdx.x, ty = threadIdx.y;
    int c0 = blockIdx.x * 32;
    int r0 = blockIdx.y * 32;
    int c  = c0 + tx;
    float mn = g_minv[c];
    float rc = g_rcp[c];
#pragma unroll
    for (int k = 0; k < 4; k++) {
        int r = r0 + ty + 8 * k;
        float v  = x[r * N_IN + c];
        float xn = __fmul_rn(__fsub_rn(v, mn), rc);   // bit-matches reference
        int j = (int)(xn * 32.0f);
        j = min(max(j, 0), 32);
        unsigned short h = __half_as_ushort(__float2half_rn(fmaxf(v, 0.0f)));
        s[ty + 8 * k][tx] = ((uint32_t)j << 16) | (uint32_t)h;
    }
    __syncthreads();
#pragma unroll
    for (int k = 0; k < 4; k++) {
        int c2 = c0 + ty + 8 * k;
        int r2 = r0 + tx;
        g_RJ[c2 * BPAD + r2] = s[tx][ty + 8 * k];
    }
}

// transpose base_weight [o][i] -> g_BW16 [i][o] fp16
__global__ void k_bw16(const float* __restrict__ bw) {
    __shared__ float s[32][33];
    int tx = threadIdx.x, ty = threadIdx.y;
    int a0 = blockIdx.y * 32;   // o
    int b0 = blockIdx.x * 32;   // i
#pragma unroll
    for (int k = 0; k < 4; k++)
        s[ty + 8 * k][tx] = bw[(a0 + ty + 8 * k) * N_IN + b0 + tx];
    __syncthreads();
#pragma unroll
    for (int k = 0; k < 4; k++)
        g_BW16[(b0 + ty + 8 * k) * N_OUT + a0 + tx] = __float2half_rn(s[tx][ty + 8 * k]);
}

// W2T[i][j<32][o] fp16
__global__ void k_w2(const float* __restrict__ sw, const float* __restrict__ sc) {
    int i = blockIdx.x;
    int o = threadIdx.x;
    float s = sc[o * N_IN + i];
    float w[N_BASES];
#pragma unroll
    for (int k = 0; k < N_BASES; k++)
        w[k] = sw[o * (N_IN * N_BASES) + i * N_BASES + k] * s;
    __half* dst = g_W2T + (size_t)i * 32 * N_OUT + o;
#pragma unroll
    for (int j = 0; j < 32; j++) {
        float a = 0.0f;
#pragma unroll
        for (int l = 0; l < 5; l++) {
            int shift = j >> (5 - l);
            int half  = (j >> (4 - l)) & 1;
            int k     = (1 << l) - 1 + shift;
            a += half ? -w[k] : w[k];
        }
        dst[j * N_OUT] = __float2half_rn(a);
    }
}

// ================= main kernel =================
// 147 CTAs x 256 threads. thread: o8 = tid&31 -> 8 outputs; warp g -> 14 rows.
// W2 slices staged to smem via cp.async (4 i per stage, double-buffered).
// Gathers via conflict-free LDS.128; fp16 HADD2/HFMA2 accumulation, f32 flush every 4 i.
__device__ __forceinline__ void fill_stage(uint32_t sdst, const char* gsrc, int tid) {
#pragma unroll
    for (int k = 0; k < 16; k++)
        cpa16(sdst + k * 4096 + tid * 16, gsrc + k * 4096 + tid * 16);
}

__global__ __launch_bounds__(256, 1) void k_main(float* __restrict__ out) {
    extern __shared__ char smem[];
    const uint32_t sb = smem_u32(smem);
    const int tid   = threadIdx.x;
    const int o8    = tid & 31;
    const int g     = tid >> 5;
    const int rbase = blockIdx.x * MTILE + g * RPW;

    if (tid < 32)
        reinterpret_cast<uint4*>(smem + SM_ZERO)[tid] = make_uint4(0, 0, 0, 0);

    unsigned long long accf[RPW][4];
    uint32_t acch[RPW][4];
#pragma unroll
    for (int r = 0; r < RPW; r++)
#pragma unroll
        for (int k = 0; k < 4; k++) { accf[r][k] = 0ull; acch[r][k] = 0u; }

    const char* w2 = reinterpret_cast<const char*>(g_W2T);
    fill_stage(sb + SM_STAGE(0), w2, tid);
    asm volatile("cp.async.commit_group;" ::: "memory");

    for (int ib = 0; ib < 64; ib++) {
        __syncthreads();                                   // readers of other stage done
        if (ib + 1 < 64)
            fill_stage(sb + SM_STAGE((ib + 1) & 1), w2 + (size_t)(ib + 1) * 65536, tid);
        asm volatile("cp.async.commit_group;" ::: "memory");
        asm volatile("cp.async.wait_group 1;" ::: "memory");
        __syncthreads();                                   // fills visible to all
        const uint32_t stg = sb + SM_STAGE(ib & 1);

#pragma unroll
        for (int u = 0; u < 4; u++) {
            const int i = ib * 4 + u;
            uint4 bwv = *reinterpret_cast<const uint4*>(
                reinterpret_cast<const char*>(g_BW16) + i * 512 + o8 * 16);
            const uint32_t* rjp = g_RJ + i * BPAD + rbase;
            const uint32_t ubase = stg + u * 16384 + o8 * 16;
#pragma unroll
            for (int r = 0; r < RPW; r++) {
                uint32_t rj = __ldg(rjp + r);              // uniform across warp
                uint32_t j  = rj >> 16;
                uint32_t a  = (j < 32) ? (ubase + j * 512) : (sb + SM_ZERO);
                uint4 gv;
                asm("ld.shared.v4.u32 {%0,%1,%2,%3}, [%4];"
                    : "=r"(gv.x), "=r"(gv.y), "=r"(gv.z), "=r"(gv.w) : "r"(a));
                uint32_t rxd;
                asm("prmt.b32 %0, %1, %1, 0x1010;" : "=r"(rxd) : "r"(rj));  // dup rx half
                hadd2a(acch[r][0], gv.x);  hfma2a(acch[r][0], bwv.x, rxd);
                hadd2a(acch[r][1], gv.y);  hfma2a(acch[r][1], bwv.y, rxd);
                hadd2a(acch[r][2], gv.z);  hfma2a(acch[r][2], bwv.z, rxd);
                hadd2a(acch[r][3], gv.w);  hfma2a(acch[r][3], bwv.w, rxd);
            }
        }
        // flush fp16 group (4 i) into f32 accumulators
#pragma unroll
        for (int r = 0; r < RPW; r++)
#pragma unroll
            for (int k = 0; k < 4; k++) {
                addf2(accf[r][k], h2f2(acch[r][k]));
                acch[r][k] = 0u;
            }
    }

#pragma unroll
    for (int r = 0; r < RPW; r++) {
        int row = rbase + r;
        if (row < NB_ROWS) {
            float4 o0, o1;
            o0.x = lo32(accf[r][0]); o0.y = hi32(accf[r][0]);
            o0.z = lo32(accf[r][1]); o0.w = hi32(accf[r][1]);
            o1.x = lo32(accf[r][2]); o1.y = hi32(accf[r][2]);
            o1.z = lo32(accf[r][3]); o1.w = hi32(accf[r][3]);
            float4* dst = reinterpret_cast<float4*>(out) + row * (N_OUT / 4) + o8 * 2;
            dst[0] = o0;
            dst[1] = o1;
        }
    }
}

// ================= launch =================
extern "C" void kernel_launch(void* const* d_in, const int* in_sizes, int n_in,
                              void* d_out, int out_size) {
    const float* x  = (const float*)d_in[0];   // [16384, 256]
    const float* bw = (const float*)d_in[1];   // [256, 256]
    const float* sw = (const float*)d_in[2];   // [256, 256, 31]
    const float* sc = (const float*)d_in[3];   // [256, 256]
    float* out = (float*)d_out;

    cudaFuncSetAttribute(k_main, cudaFuncAttributeMaxDynamicSharedMemorySize, SMEM_TOTAL);

    k_init  <<<1, 256>>>();
    k_minmax<<<128, 256>>>(x);
    k_denom <<<1, 256>>>();
    k_rxj   <<<dim3(8, NB_ROWS / 32), dim3(32, 8)>>>(x);
    k_bw16  <<<dim3(8, 8), dim3(32, 8)>>>(bw);
    k_w2    <<<256, 256>>>(sw, sc);
    k_main  <<<NCTA, 256, SMEM_TOTAL>>>(out);
}

// round 8
// speedup vs baseline: 1.4948x; 1.0133x over previous
#include <cuda_runtime.h>
#include <cuda_fp16.h>
#include <cstdint>

// ================= problem constants =================
#define NB_ROWS  16384
#define N_IN     256
#define N_OUT    256
#define N_BASES  31
#define MTILE    112                 // rows per CTA
#define RPW      7                   // rows per warp (16 warps)
#define NCTA     147                 // ceil(16384/112)
#define BPAD     16576               // padded rows (mult of 32, >= 147*112)
#define THREADS  512

// W2 slice: 33 j-rows (32 real + zero row for j=32) x 256 fp16 = 16896 B
#define SLICE    16896
#define STAGE    (4 * SLICE)         // 67584 B: 4 i per stage
#define SMEM_TOTAL (2 * STAGE)       // 135168 B double-buffered

// ================= device scratch =================
__device__ __align__(16) __half   g_W2T[N_IN * 33 * N_OUT];  // [i][j<=32][o] fp16, 4.3 MB
__device__ __align__(16) __half   g_BW16[N_IN * N_OUT];      // [i][o] fp16
__device__ uint32_t               g_RJ[N_IN * BPAD];         // [i][row]: (j<<16)|rx_fp16
__device__ unsigned int g_minU[N_IN];
__device__ unsigned int g_maxU[N_IN];
__device__ float        g_minv[N_IN];
__device__ float        g_rcp[N_IN];

// ================= helpers =================
__device__ __forceinline__ unsigned int enc_f(float f) {
    unsigned int u = __float_as_uint(f);
    return (u & 0x80000000u) ? ~u : (u | 0x80000000u);
}
__device__ __forceinline__ float dec_f(unsigned int e) {
    unsigned int u = (e & 0x80000000u) ? (e ^ 0x80000000u) : ~e;
    return __uint_as_float(u);
}
__device__ __forceinline__ uint32_t smem_u32(const void* p) {
    uint32_t a;
    asm("{ .reg .u64 t; cvta.to.shared.u64 t, %1; cvt.u32.u64 %0, t; }" : "=r"(a) : "l"(p));
    return a;
}
__device__ __forceinline__ unsigned long long pk2(float a, float b) {
    unsigned long long r;
    asm("mov.b64 %0, {%1, %2};" : "=l"(r) : "f"(a), "f"(b));
    return r;
}
__device__ __forceinline__ void addf2(unsigned long long& d, unsigned long long a) {
    asm("add.rn.f32x2 %0, %1, %0;" : "+l"(d) : "l"(a));
}
__device__ __forceinline__ float lo32(unsigned long long v) {
    return __uint_as_float((unsigned int)(v & 0xFFFFFFFFull));
}
__device__ __forceinline__ float hi32(unsigned long long v) {
    return __uint_as_float((unsigned int)(v >> 32));
}
__device__ __forceinline__ void hadd2a(uint32_t& acc, uint32_t v) {
    asm("add.rn.f16x2 %0, %1, %0;" : "+r"(acc) : "r"(v));
}
__device__ __forceinline__ void hfma2a(uint32_t& acc, uint32_t a, uint32_t b) {
    asm("fma.rn.f16x2 %0, %1, %2, %0;" : "+r"(acc) : "r"(a), "r"(b));
}
__device__ __forceinline__ unsigned long long h2f2(uint32_t h) {
    __half2 hh = *reinterpret_cast<__half2*>(&h);
    float2 f = __half22float2(hh);
    return pk2(f.x, f.y);
}
__device__ __forceinline__ void cpa16(uint32_t saddr, const void* g) {
    asm volatile("cp.async.cg.shared.global [%0], [%1], 16;" :: "r"(saddr), "l"(g));
}

// ================= prep kernels =================
__global__ void k_init() {
    int t = threadIdx.x;
    g_minU[t] = 0xFFFFFFFFu;
    g_maxU[t] = 0x00000000u;
}

__global__ void k_minmax(const float* __restrict__ x) {
    int c  = threadIdx.x;
    int r0 = blockIdx.x * 128;
    float mn = __int_as_float(0x7f800000);
    float mx = __int_as_float(0xff800000);
    for (int r = r0; r < r0 + 128; r++) {
        float v = x[r * N_IN + c];
        mn = fminf(mn, v);
        mx = fmaxf(mx, v);
    }
    atomicMin(&g_minU[c], enc_f(mn));
    atomicMax(&g_maxU[c], enc_f(mx));
}

__global__ void k_denom() {   // XLA rewrites div(A,bcast(B)) -> mul(A,bcast(1/B))
    int i = threadIdx.x;
    float mn = dec_f(g_minU[i]);
    float mx = dec_f(g_maxU[i]);
    float d  = __fadd_rn(__fsub_rn(mx, mn), 1e-8f);
    g_minv[i] = mn;
    g_rcp[i]  = __frcp_rn(d);
}

// bucketize + relu fp16, transposed -> g_RJ[i][row] = (j<<16)|rx_h
__global__ void k_rxj(const float* __restrict__ x) {
    __shared__ uint32_t s[32][33];
    int tx = threadIdx.x, ty = threadIdx.y;
    int c0 = blockIdx.x * 32;
    int r0 = blockIdx.y * 32;
    int c  = c0 + tx;
    float mn = g_minv[c];
    float rc = g_rcp[c];
#pragma unroll
    for (int k = 0; k < 4; k++) {
        int r = r0 + ty + 8 * k;
        float v  = x[r * N_IN + c];
        float xn = __fmul_rn(__fsub_rn(v, mn), rc);   // bit-matches reference
        int j = (int)(xn * 32.0f);
        j = min(max(j, 0), 32);
        unsigned short h = __half_as_ushort(__float2half_rn(fmaxf(v, 0.0f)));
        s[ty + 8 * k][tx] = ((uint32_t)j << 16) | (uint32_t)h;
    }
    __syncthreads();
#pragma unroll
    for (int k = 0; k < 4; k++) {
        int c2 = c0 + ty + 8 * k;
        int r2 = r0 + tx;
        g_RJ[c2 * BPAD + r2] = s[tx][ty + 8 * k];
    }
}

// transpose base_weight [o][i] -> g_BW16 [i][o] fp16
__global__ void k_bw16(const float* __restrict__ bw) {
    __shared__ float s[32][33];
    int tx = threadIdx.x, ty = threadIdx.y;
    int a0 = blockIdx.y * 32;   // o
    int b0 = blockIdx.x * 32;   // i
#pragma unroll
    for (int k = 0; k < 4; k++)
        s[ty + 8 * k][tx] = bw[(a0 + ty + 8 * k) * N_IN + b0 + tx];
    __syncthreads();
#pragma unroll
    for (int k = 0; k < 4; k++)
        g_BW16[(b0 + ty + 8 * k) * N_OUT + a0 + tx] = __float2half_rn(s[tx][ty + 8 * k]);
}

// W2T[i][j<=32][o] fp16 (j=32 row is zeros)
__global__ void k_w2(const float* __restrict__ sw, const float* __restrict__ sc) {
    int i = blockIdx.x;
    int o = threadIdx.x;
    float s = sc[o * N_IN + i];
    float w[N_BASES];
#pragma unroll
    for (int k = 0; k < N_BASES; k++)
        w[k] = sw[o * (N_IN * N_BASES) + i * N_BASES + k] * s;
    __half* dst = g_W2T + (size_t)i * 33 * N_OUT + o;
#pragma unroll
    for (int j = 0; j < 32; j++) {
        float a = 0.0f;
#pragma unroll
        for (int l = 0; l < 5; l++) {
            int shift = j >> (5 - l);
            int half  = (j >> (4 - l)) & 1;
            int k     = (1 << l) - 1 + shift;
            a += half ? -w[k] : w[k];
        }
        dst[j * N_OUT] = __float2half_rn(a);
    }
    dst[32 * N_OUT] = __ushort_as_half(0);   // zero row for j == 32
}

// ================= main kernel =================
// 147 CTAs x 512 threads (16 warps). lane o8 -> 8 outputs; warp w -> 7 rows.
// W2 slices (incl. zero row) staged via cp.async double-buffer, 4 i per stage.
__device__ __forceinline__ void fill_stage(uint32_t sdst, const char* gsrc, int tid) {
    for (int k = tid; k < STAGE / 16; k += THREADS)
        cpa16(sdst + k * 16, gsrc + k * 16);
}

__global__ __launch_bounds__(THREADS, 1) void k_main(float* __restrict__ out) {
    extern __shared__ char smem[];
    const uint32_t sb = smem_u32(smem);
    const int tid   = threadIdx.x;
    const int o8    = tid & 31;
    const int w     = tid >> 5;
    const int rbase = blockIdx.x * MTILE + w * RPW;

    unsigned long long accf[RPW][4];
    uint32_t acch[RPW][4];
#pragma unroll
    for (int r = 0; r < RPW; r++)
#pragma unroll
        for (int k = 0; k < 4; k++) { accf[r][k] = 0ull; acch[r][k] = 0u; }

    const char* w2 = reinterpret_cast<const char*>(g_W2T);
    fill_stage(sb, w2, tid);
    asm volatile("cp.async.commit_group;" ::: "memory");

    for (int ib = 0; ib < 64; ib++) {
        __syncthreads();                                   // readers of other stage done
        if (ib + 1 < 64)
            fill_stage(sb + ((ib + 1) & 1) * STAGE, w2 + (size_t)(ib + 1) * STAGE, tid);
        asm volatile("cp.async.commit_group;" ::: "memory");
        asm volatile("cp.async.wait_group 1;" ::: "memory");
        __syncthreads();                                   // fills visible to all
        const uint32_t stg = sb + (ib & 1) * STAGE;

#pragma unroll
        for (int u = 0; u < 4; u++) {
            const int i = ib * 4 + u;
            uint4 bwv = *reinterpret_cast<const uint4*>(
                reinterpret_cast<const char*>(g_BW16) + i * 512 + o8 * 16);
            const uint32_t* rjp = g_RJ + i * BPAD + rbase;
            const uint32_t ubase = stg + u * SLICE + o8 * 16;
#pragma unroll
            for (int r = 0; r < RPW; r++) {
                uint32_t rj = __ldg(rjp + r);              // uniform across warp
                uint32_t a  = ubase + (rj >> 16) * 512;    // j==32 hits zero row
                uint4 gv;
                asm("ld.shared.v4.u32 {%0,%1,%2,%3}, [%4];"
                    : "=r"(gv.x), "=r"(gv.y), "=r"(gv.z), "=r"(gv.w) : "r"(a));
                uint32_t rxd;
                asm("prmt.b32 %0, %1, %1, 0x1010;" : "=r"(rxd) : "r"(rj));  // splat rx half
                hadd2a(acch[r][0], gv.x);  hfma2a(acch[r][0], bwv.x, rxd);
                hadd2a(acch[r][1], gv.y);  hfma2a(acch[r][1], bwv.y, rxd);
                hadd2a(acch[r][2], gv.z);  hfma2a(acch[r][2], bwv.z, rxd);
                hadd2a(acch[r][3], gv.w);  hfma2a(acch[r][3], bwv.w, rxd);
            }
        }
        // flush fp16 group (4 i) into f32 accumulators
#pragma unroll
        for (int r = 0; r < RPW; r++)
#pragma unroll
            for (int k = 0; k < 4; k++) {
                addf2(accf[r][k], h2f2(acch[r][k]));
                acch[r][k] = 0u;
            }
    }

#pragma unroll
    for (int r = 0; r < RPW; r++) {
        int row = rbase + r;
        if (row < NB_ROWS) {
            float4 o0, o1;
            o0.x = lo32(accf[r][0]); o0.y = hi32(accf[r][0]);
            o0.z = lo32(accf[r][1]); o0.w = hi32(accf[r][1]);
            o1.x = lo32(accf[r][2]); o1.y = hi32(accf[r][2]);
            o1.z = lo32(accf[r][3]); o1.w = hi32(accf[r][3]);
            float4* dst = reinterpret_cast<float4*>(out) + row * (N_OUT / 4) + o8 * 2;
            dst[0] = o0;
            dst[1] = o1;
        }
    }
}

// ================= launch =================
extern "C" void kernel_launch(void* const* d_in, const int* in_sizes, int n_in,
                              void* d_out, int out_size) {
    const float* x  = (const float*)d_in[0];   // [16384, 256]
    const float* bw = (const float*)d_in[1];   // [256, 256]
    const float* sw = (const float*)d_in[2];   // [256, 256, 31]
    const float* sc = (const float*)d_in[3];   // [256, 256]
    float* out = (float*)d_out;

    cudaFuncSetAttribute(k_main, cudaFuncAttributeMaxDynamicSharedMemorySize, SMEM_TOTAL);

    k_init  <<<1, 256>>>();
    k_minmax<<<128, 256>>>(x);
    k_denom <<<1, 256>>>();
    k_rxj   <<<dim3(8, NB_ROWS / 32), dim3(32, 8)>>>(x);
    k_bw16  <<<dim3(8, 8), dim3(32, 8)>>>(bw);
    k_w2    <<<256, 256>>>(sw, sc);
    k_main  <<<NCTA, THREADS, SMEM_TOTAL>>>(out);
}

// round 9
// speedup vs baseline: 1.7351x; 1.1607x over previous
#include <cuda_runtime.h>
#include <cuda_fp16.h>
#include <cstdint>

// ================= problem constants =================
#define NB_ROWS  16384
#define N_IN     256
#define N_OUT    256
#define N_BASES  31
#define MTILE    112                 // rows per CTA
#define RPW      7                   // rows per warp (16 warps)
#define NCTA     147                 // ceil(16384/112)
#define BROWS    (NCTA * MTILE)      // 16464 padded rows
#define THREADS  512

// W2 slice: 33 j-rows (32 real + zero row for j=32) x 256 fp16 = 16896 B
#define SLICE    16896
#define STAGE    (4 * SLICE)         // 67584 B: 4 i per stage
#define SM_MBAR  (2 * STAGE)         // two 8B mbarriers after the stages
#define SMEM_TOTAL (2 * STAGE + 64)

// ================= device scratch =================
__device__ __align__(16) __half   g_W2T[N_IN * 33 * N_OUT];  // [i][j<=32][o] fp16, 4.3 MB
__device__ __align__(16) __half   g_BW16[N_IN * N_OUT];      // [i][o] fp16
__device__ __align__(16) uint32_t g_RJ2[BROWS * N_IN];       // [row][i]: (j<<16)|rx_fp16
__device__ unsigned int g_minU[N_IN];
__device__ unsigned int g_maxU[N_IN];
__device__ float        g_minv[N_IN];
__device__ float        g_rcp[N_IN];

// ================= helpers =================
__device__ __forceinline__ unsigned int enc_f(float f) {
    unsigned int u = __float_as_uint(f);
    return (u & 0x80000000u) ? ~u : (u | 0x80000000u);
}
__device__ __forceinline__ float dec_f(unsigned int e) {
    unsigned int u = (e & 0x80000000u) ? (e ^ 0x80000000u) : ~e;
    return __uint_as_float(u);
}
__device__ __forceinline__ uint32_t smem_u32(const void* p) {
    uint32_t a;
    asm("{ .reg .u64 t; cvta.to.shared.u64 t, %1; cvt.u32.u64 %0, t; }" : "=r"(a) : "l"(p));
    return a;
}
__device__ __forceinline__ unsigned long long pk2(float a, float b) {
    unsigned long long r;
    asm("mov.b64 %0, {%1, %2};" : "=l"(r) : "f"(a), "f"(b));
    return r;
}
__device__ __forceinline__ void addf2(unsigned long long& d, unsigned long long a) {
    asm("add.rn.f32x2 %0, %1, %0;" : "+l"(d) : "l"(a));
}
__device__ __forceinline__ float lo32(unsigned long long v) {
    return __uint_as_float((unsigned int)(v & 0xFFFFFFFFull));
}
__device__ __forceinline__ float hi32(unsigned long long v) {
    return __uint_as_float((unsigned int)(v >> 32));
}
__device__ __forceinline__ void hadd2a(uint32_t& acc, uint32_t v) {
    asm("add.rn.f16x2 %0, %1, %0;" : "+r"(acc) : "r"(v));
}
__device__ __forceinline__ void hfma2a(uint32_t& acc, uint32_t a, uint32_t b) {
    asm("fma.rn.f16x2 %0, %1, %2, %0;" : "+r"(acc) : "r"(a), "r"(b));
}
__device__ __forceinline__ unsigned long long h2f2(uint32_t h) {
    __half2 hh = *reinterpret_cast<__half2*>(&h);
    float2 f = __half22float2(hh);
    return pk2(f.x, f.y);
}

#define MBAR_INIT(a, c)  asm volatile("mbarrier.init.shared.b64 [%0], %1;" :: "r"(a), "r"(c) : "memory")
#define MBAR_EXPECT(a, b) asm volatile("mbarrier.arrive.expect_tx.shared.b64 _, [%0], %1;" :: "r"(a), "r"(b) : "memory")
#define MBAR_WAIT(a, ph) do {                                                        \
    uint32_t _m = (a), _p = (ph), _d;                                                \
    asm volatile("{\n\t.reg .pred p;\n\t"                                            \
        "mbarrier.try_wait.parity.acquire.cta.shared::cta.b64 p, [%1], %2;\n\t"      \
        "selp.b32 %0,1,0,p;\n\t}" : "=r"(_d) : "r"(_m), "r"(_p) : "memory");         \
    if (!_d) {                                                                       \
        asm volatile("{\n\t.reg .pred P1;\n\tWL_%=:\n\t"                             \
            "mbarrier.try_wait.parity.acquire.cta.shared::cta.b64 P1, [%0], %1, 0x989680;\n\t" \
            "@P1 bra.uni WD_%=;\n\tbra.uni WL_%=;\n\tWD_%=:\n\t}"                    \
            :: "r"(_m), "r"(_p) : "memory");                                         \
    }                                                                                \
} while (0)
#define BULK_CP(dst, src, bytes, mbar) \
    asm volatile("cp.async.bulk.shared::cluster.global.mbarrier::complete_tx::bytes [%0], [%1], %2, [%3];" \
        :: "r"(dst), "l"(src), "r"(bytes), "r"(mbar) : "memory")

// ================= prep kernels =================
__global__ void k_init() {
    int t = threadIdx.x;
    g_minU[t] = 0xFFFFFFFFu;
    g_maxU[t] = 0x00000000u;
}

__global__ void k_minmax(const float* __restrict__ x) {
    int c  = threadIdx.x;
    int r0 = blockIdx.x * 128;
    float mn = __int_as_float(0x7f800000);
    float mx = __int_as_float(0xff800000);
    for (int r = r0; r < r0 + 128; r++) {
        float v = x[r * N_IN + c];
        mn = fminf(mn, v);
        mx = fmaxf(mx, v);
    }
    atomicMin(&g_minU[c], enc_f(mn));
    atomicMax(&g_maxU[c], enc_f(mx));
}

__global__ void k_denom() {   // XLA rewrites div(A,bcast(B)) -> mul(A,bcast(1/B))
    int i = threadIdx.x;
    float mn = dec_f(g_minU[i]);
    float mx = dec_f(g_maxU[i]);
    float d  = __fadd_rn(__fsub_rn(mx, mn), 1e-8f);
    g_minv[i] = mn;
    g_rcp[i]  = __frcp_rn(d);
}

// bucketize + relu fp16 -> g_RJ2[row][i] (coalesced in and out, no transpose)
__global__ void k_rxj(const float* __restrict__ x) {
    int i  = threadIdx.x;
    int r0 = blockIdx.x * 8;
    float mn = g_minv[i];
    float rc = g_rcp[i];
#pragma unroll
    for (int k = 0; k < 8; k++) {
        int idx = (r0 + k) * N_IN + i;
        float v  = x[idx];
        float xn = __fmul_rn(__fsub_rn(v, mn), rc);   // bit-matches reference
        int j = (int)(xn * 32.0f);
        j = min(max(j, 0), 32);
        unsigned short h = __half_as_ushort(__float2half_rn(fmaxf(v, 0.0f)));
        g_RJ2[idx] = ((uint32_t)j << 16) | (uint32_t)h;
    }
}

// pad rows [16384, 16464): j=32 (zero W2 row), rx=0
__global__ void k_pad() {
    g_RJ2[(NB_ROWS + blockIdx.x) * N_IN + threadIdx.x] = (32u << 16);
}

// transpose base_weight [o][i] -> g_BW16 [i][o] fp16
__global__ void k_bw16(const float* __restrict__ bw) {
    __shared__ float s[32][33];
    int tx = threadIdx.x, ty = threadIdx.y;
    int a0 = blockIdx.y * 32;   // o
    int b0 = blockIdx.x * 32;   // i
#pragma unroll
    for (int k = 0; k < 4; k++)
        s[ty + 8 * k][tx] = bw[(a0 + ty + 8 * k) * N_IN + b0 + tx];
    __syncthreads();
#pragma unroll
    for (int k = 0; k < 4; k++)
        g_BW16[(b0 + ty + 8 * k) * N_OUT + a0 + tx] = __float2half_rn(s[tx][ty + 8 * k]);
}

// W2T[i][j<=32][o] fp16 (j=32 row is zeros)
__global__ void k_w2(const float* __restrict__ sw, const float* __restrict__ sc) {
    int i = blockIdx.x;
    int o = threadIdx.x;
    float s = sc[o * N_IN + i];
    float w[N_BASES];
#pragma unroll
    for (int k = 0; k < N_BASES; k++)
        w[k] = sw[o * (N_IN * N_BASES) + i * N_BASES + k] * s;
    __half* dst = g_W2T + (size_t)i * 33 * N_OUT + o;
#pragma unroll
    for (int j = 0; j < 32; j++) {
        float a = 0.0f;
#pragma unroll
        for (int l = 0; l < 5; l++) {
            int shift = j >> (5 - l);
            int half  = (j >> (4 - l)) & 1;
            int k     = (1 << l) - 1 + shift;
            a += half ? -w[k] : w[k];
        }
        dst[j * N_OUT] = __float2half_rn(a);
    }
    dst[32 * N_OUT] = __ushort_as_half(0);   // zero row for j == 32
}

// ================= main kernel =================
// 147 CTAs x 512 threads (16 warps). lane o8 -> 8 outputs; warp w -> 7 rows.
// Stage fill: ONE cp.async.bulk (TMA) per 4-i stage, double-buffered w/ mbarriers.
// Per stage per warp: 7 uniform LDG.128 (rj for 4 i) + 28 LDS.128 gathers.
__global__ __launch_bounds__(THREADS, 1) void k_main(float* __restrict__ out) {
    extern __shared__ char smem[];
    const uint32_t sb = smem_u32(smem);
    const int tid   = threadIdx.x;
    const int o8    = tid & 31;
    const int w     = tid >> 5;
    const int rbase = blockIdx.x * MTILE + w * RPW;

    if (tid == 0) {
        MBAR_INIT(sb + SM_MBAR,     1);
        MBAR_INIT(sb + SM_MBAR + 8, 1);
    }
    __syncthreads();

    unsigned long long accf[RPW][4];
    uint32_t acch[RPW][4];
#pragma unroll
    for (int r = 0; r < RPW; r++)
#pragma unroll
        for (int k = 0; k < 4; k++) { accf[r][k] = 0ull; acch[r][k] = 0u; }

    const char* w2 = reinterpret_cast<const char*>(g_W2T);
    if (tid == 0) {
        MBAR_EXPECT(sb + SM_MBAR, STAGE);
        BULK_CP(sb, w2, STAGE, sb + SM_MBAR);
    }

    for (int ib = 0; ib < 64; ib++) {
        __syncthreads();                       // readers of the other stage done
        if (tid == 0 && ib + 1 < 64) {
            uint32_t mb = sb + SM_MBAR + 8 * ((ib + 1) & 1);
            MBAR_EXPECT(mb, STAGE);
            BULK_CP(sb + ((ib + 1) & 1) * STAGE, w2 + (size_t)(ib + 1) * STAGE, STAGE, mb);
        }
        MBAR_WAIT(sb + SM_MBAR + 8 * (ib & 1), (ib >> 1) & 1);
        const uint32_t stg = sb + (ib & 1) * STAGE;

        // base weights for the 4 i of this stage
        uint4 bwv[4];
#pragma unroll
        for (int u = 0; u < 4; u++)
            bwv[u] = *reinterpret_cast<const uint4*>(
                reinterpret_cast<const char*>(g_BW16) + (ib * 4 + u) * 512 + o8 * 16);

#pragma unroll
        for (int r = 0; r < RPW; r++) {
            // one uniform LDG.128: rj for 4 consecutive i of row rbase+r
            uint4 q = __ldg(reinterpret_cast<const uint4*>(g_RJ2 + (size_t)(rbase + r) * N_IN) + ib);
            uint32_t qa[4] = { q.x, q.y, q.z, q.w };
#pragma unroll
            for (int u = 0; u < 4; u++) {
                uint32_t rj = qa[u];
                uint32_t a  = stg + u * SLICE + (rj >> 16) * 512 + o8 * 16;  // j==32 -> zero row
                uint4 gv;
                asm("ld.shared.v4.u32 {%0,%1,%2,%3}, [%4];"
                    : "=r"(gv.x), "=r"(gv.y), "=r"(gv.z), "=r"(gv.w) : "r"(a));
                uint32_t rxd;
                asm("prmt.b32 %0, %1, %1, 0x1010;" : "=r"(rxd) : "r"(rj));   // splat rx half
                hadd2a(acch[r][0], gv.x);  hfma2a(acch[r][0], bwv[u].x, rxd);
                hadd2a(acch[r][1], gv.y);  hfma2a(acch[r][1], bwv[u].y, rxd);
                hadd2a(acch[r][2], gv.z);  hfma2a(acch[r][2], bwv[u].z, rxd);
                hadd2a(acch[r][3], gv.w);  hfma2a(acch[r][3], bwv[u].w, rxd);
            }
        }
        // flush fp16 group (4 i) into f32 accumulators
#pragma unroll
        for (int r = 0; r < RPW; r++)
#pragma unroll
            for (int k = 0; k < 4; k++) {
                addf2(accf[r][k], h2f2(acch[r][k]));
                acch[r][k] = 0u;
            }
    }

#pragma unroll
    for (int r = 0; r < RPW; r++) {
        int row = rbase + r;
        if (row < NB_ROWS) {
            float4 o0, o1;
            o0.x = lo32(accf[r][0]); o0.y = hi32(accf[r][0]);
            o0.z = lo32(accf[r][1]); o0.w = hi32(accf[r][1]);
            o1.x = lo32(accf[r][2]); o1.y = hi32(accf[r][2]);
            o1.z = lo32(accf[r][3]); o1.w = hi32(accf[r][3]);
            float4* dst = reinterpret_cast<float4*>(out) + row * (N_OUT / 4) + o8 * 2;
            dst[0] = o0;
            dst[1] = o1;
        }
    }
}

// ================= launch =================
extern "C" void kernel_launch(void* const* d_in, const int* in_sizes, int n_in,
                              void* d_out, int out_size) {
    const float* x  = (const float*)d_in[0];   // [16384, 256]
    const float* bw = (const float*)d_in[1];   // [256, 256]
    const float* sw = (const float*)d_in[2];   // [256, 256, 31]
    const float* sc = (const float*)d_in[3];   // [256, 256]
    float* out = (float*)d_out;

    cudaFuncSetAttribute(k_main, cudaFuncAttributeMaxDynamicSharedMemorySize, SMEM_TOTAL);

    k_init  <<<1, 256>>>();
    k_minmax<<<128, 256>>>(x);
    k_denom <<<1, 256>>>();
    k_rxj   <<<NB_ROWS / 8, 256>>>(x);
    k_pad   <<<BROWS - NB_ROWS, 256>>>();
    k_bw16  <<<dim3(8, 8), dim3(32, 8)>>>(bw);
    k_w2    <<<256, 256>>>(sw, sc);
    k_main  <<<NCTA, THREADS, SMEM_TOTAL>>>(out);
}